// round 7
// baseline (speedup 1.0000x reference)
#include <cuda_runtime.h>
#include <cuda_fp16.h>
#include <cstdint>

#define NT 256
#define BM 64

// fp16 fragment-packed weights: [hW2 | fW2 | fW3], written by prepack kernel.
// Big GEMMs: idx = g*32768 + ((kk*32+nf)*32+lane)*2+br   (32768 u32 each).
// fW3:       idx = 65536 + ((kk*2+nf)*32+lane)*2+br      (2048 u32 = 8KB).
__device__ __align__(16) uint32_t g_wpk[2 * 32768 + 2048];

// ---- smem byte offsets ----
#define O_SA   0u        // 32KB activations, fragment-major half2 [strip][kk][lane][slot]
#define O_WH   32768u    // hW1^T [16][256] f32
#define O_WF   49152u    // fW1^T [16][256] f32
#define O_W3   65536u    // fW3 fragments (8KB: 2048 u32)
#define O_HB1  73728u    // hb1 f32[256]
#define O_HB2  74752u    // hb2 half[256]
#define O_FB1  75264u    // fb1 half[256]
#define O_FB2  75776u    // fb2 half[256]
#define O_FB3  76288u    // fb3 f32[16]
#define SMEMB  76352

__device__ __forceinline__ float fast_tanh(float x) {
    float e = __expf(2.0f * x);
    return 1.0f - __fdividef(2.0f, e + 1.0f);
}
__device__ __forceinline__ uint32_t h2u(float lo, float hi) {
    uint32_t r;
    asm("{ .reg .b16 l, h; cvt.rn.f16.f32 l, %1; cvt.rn.f16.f32 h, %2; mov.b32 %0, {l, h}; }"
        : "=r"(r) : "f"(lo), "f"(hi));
    return r;
}
__device__ __forceinline__ void mma16816(float d[4],
    uint32_t a0, uint32_t a1, uint32_t a2, uint32_t a3, uint32_t b0, uint32_t b1) {
    asm volatile("mma.sync.aligned.m16n8k16.row.col.f32.f16.f16.f32 "
                 "{%0,%1,%2,%3},{%4,%5,%6,%7},{%8,%9},{%0,%1,%2,%3};"
                 : "+f"(d[0]), "+f"(d[1]), "+f"(d[2]), "+f"(d[3])
                 : "r"(a0), "r"(a1), "r"(a2), "r"(a3), "r"(b0), "r"(b1));
}

// ---------- prepack: hW2/fW2/fW3 -> fp16 fragment order ----------
__global__ void __launch_bounds__(512) prepack(const float* __restrict__ hW2,
                                               const float* __restrict__ fW2,
                                               const float* __restrict__ fW3) {
    int tid = blockIdx.x * 512 + threadIdx.x;
    if (tid < 65536) {
        int off = tid & 32767;
        const float* W = (tid >> 15) ? fW2 : hW2;
        int br = off & 1, lane = (off >> 1) & 31, nf = (off >> 6) & 31, kk = off >> 11;
        int n = nf * 8 + (lane >> 2), k = kk * 16 + 2 * (lane & 3) + br * 8;
        g_wpk[tid] = h2u(W[n * 256 + k], W[n * 256 + k + 1]);
    } else if (tid < 67584) {
        int off = tid - 65536;
        int br = off & 1, lane = (off >> 1) & 31, nf = (off >> 6) & 1, kk = off >> 7;
        int n = nf * 8 + (lane >> 2), k = kk * 16 + 2 * (lane & 3) + br * 8;
        g_wpk[tid] = h2u(fW3[n * 256 + k], fW3[n * 256 + k + 1]);
    }
}

// big GEMM: A frags from smem, B frags streamed from L2-resident g_wpk
__device__ __forceinline__ void gemm_big(const uint4* __restrict__ sa4,
                                         const uint32_t* __restrict__ wg,
                                         int wrow, int wcol, int lane,
                                         float acc[2][8][4]) {
    const int s0 = wrow * 2, nfb = wcol * 8;
#pragma unroll
    for (int kk = 0; kk < 16; ++kk) {
        uint4 A0 = sa4[(s0 * 16 + kk) * 32 + lane];
        uint4 A1 = sa4[((s0 + 1) * 16 + kk) * 32 + lane];
        uint2 B[8];
#pragma unroll
        for (int nt = 0; nt < 8; ++nt)
            B[nt] = *(const uint2*)(wg + (size_t)((kk * 32 + nfb + nt) * 32 + lane) * 2);
#pragma unroll
        for (int nt = 0; nt < 8; ++nt) {
            mma16816(acc[0][nt], A0.x, A0.y, A0.z, A0.w, B[nt].x, B[nt].y);
            mma16816(acc[1][nt], A1.x, A1.y, A1.z, A1.w, B[nt].x, B[nt].y);
        }
    }
}

__global__ void __launch_bounds__(NT, 2)
flexhnn_f16(const float* __restrict__ z,
            const float* __restrict__ hW1, const float* __restrict__ hb1,
            const float* __restrict__ hb2,
            const float* __restrict__ fW1, const float* __restrict__ fb1,
            const float* __restrict__ fb2, const float* __restrict__ fb3,
            float* __restrict__ out)
{
    extern __shared__ __align__(16) char smx[];
    uint32_t* smU = (uint32_t*)smx;
    float*    smF = (float*)smx;
    const uint4* sa4 = (const uint4*)(smx + O_SA);

    const int t = threadIdx.x, lane = t & 31, w = t >> 5;
    const int fr = lane >> 2, fc = lane & 3;
    const int wrow = w & 1, wcol = w >> 1;
    const int nq = wcol * 64;
    const long n0 = (long)blockIdx.x * BM;

    // ---------------- stage: hW1^T, fW1^T, fW3 frags, biases ----------------
#pragma unroll
    for (int p = 0; p < 4; ++p) {
        int idx = p * NT + t;                // 0..1023 float4s
        int j = idx >> 2, d4 = (idx & 3) * 4;
        float4 a = *(const float4*)(hW1 + j * 16 + d4);
        smF[O_WH / 4 + (d4 + 0) * 256 + j] = a.x;
        smF[O_WH / 4 + (d4 + 1) * 256 + j] = a.y;
        smF[O_WH / 4 + (d4 + 2) * 256 + j] = a.z;
        smF[O_WH / 4 + (d4 + 3) * 256 + j] = a.w;
        float4 b = *(const float4*)(fW1 + j * 16 + d4);
        smF[O_WF / 4 + (d4 + 0) * 256 + j] = b.x;
        smF[O_WF / 4 + (d4 + 1) * 256 + j] = b.y;
        smF[O_WF / 4 + (d4 + 2) * 256 + j] = b.z;
        smF[O_WF / 4 + (d4 + 3) * 256 + j] = b.w;
    }
    {   // fW3 frags: 512 uint4 = 8KB
        ((uint4*)(smx + O_W3))[t]       = ((const uint4*)(g_wpk + 65536))[t];
        ((uint4*)(smx + O_W3))[t + 256] = ((const uint4*)(g_wpk + 65536))[t + 256];
    }
    {
        smF[O_HB1 / 4 + t] = hb1[t];
        ((__half*)(smx + O_HB2))[t] = __float2half(hb2[t]);
        ((__half*)(smx + O_FB1))[t] = __float2half(fb1[t]);
        ((__half*)(smx + O_FB2))[t] = __float2half(fb2[t]);
        if (t < 16) smF[O_FB3 / 4 + t] = fb3[t];
    }
    __syncthreads();

    // ---------------- epi1: t1 = tanh(z @ hW1^T + hb1) -> sA frags ----------------
    {
        const int r0 = (t >> 4) * 4, cp2 = t & 15;
        float4 z4[4][4];
#pragma unroll
        for (int i = 0; i < 4; ++i)
#pragma unroll
            for (int q = 0; q < 4; ++q)
                z4[i][q] = *(const float4*)(z + (n0 + r0 + i) * 16 + q * 4);
#pragma unroll
        for (int p = 0; p < 8; ++p) {
            const int c0 = p * 32 + cp2 * 2;
            float fa[4][2];
            const float b0 = smF[O_HB1 / 4 + c0], b1 = smF[O_HB1 / 4 + c0 + 1];
#pragma unroll
            for (int i = 0; i < 4; ++i) { fa[i][0] = b0; fa[i][1] = b1; }
#pragma unroll
            for (int d = 0; d < 16; ++d) {
                float2 wv = *(const float2*)(smF + O_WH / 4 + d * 256 + c0);
#pragma unroll
                for (int i = 0; i < 4; ++i) {
                    float zv = ((const float*)&z4[i][d >> 2])[d & 3];
                    fa[i][0] = fmaf(zv, wv.x, fa[i][0]);
                    fa[i][1] = fmaf(zv, wv.y, fa[i][1]);
                }
            }
            const int kk = c0 >> 4, cp = (c0 & 15) >> 1;
            const int slotc = (cp >= 4) ? 2 : 0, fcc = cp & 3;
#pragma unroll
            for (int i = 0; i < 4; ++i) {
                int r = r0 + i;
                uint32_t v = h2u(fast_tanh(fa[i][0]), fast_tanh(fa[i][1]));
                int strip = r >> 4;
                int lanep = (r & 7) * 4 + fcc;
                int slot = ((r & 15) >> 3) + slotc;
                smU[O_SA / 4 + ((strip * 16 + kk) * 32 + lanep) * 4 + slot] = v;
            }
        }
    }
    __syncthreads();

    // ---------------- GEMM2: a2 = t1 @ hW2^T (B from L2) ----------------
    float acc[2][8][4];
#pragma unroll
    for (int mt = 0; mt < 2; ++mt)
#pragma unroll
        for (int nt = 0; nt < 8; ++nt)
#pragma unroll
            for (int i = 0; i < 4; ++i) acc[mt][nt][i] = 0.0f;
    gemm_big(sa4, g_wpk, wrow, wcol, lane, acc);
    __syncthreads();                          // all sA reads done before overwrite

    // ---------------- epi2 (register): g = .5*f*s2 + .5*tanh(f) -> sA ----------------
    {
        const __half* hb2h = (const __half*)(smx + O_HB2);
        const __half* fb1h = (const __half*)(smx + O_FB1);
#pragma unroll
        for (int mt = 0; mt < 2; ++mt) {
            const int rbase = wrow * 32 + mt * 16;
            const int strip = wrow * 2 + mt;
            float4 zlo[4], zhi[4];
#pragma unroll
            for (int q = 0; q < 4; ++q) {
                zlo[q] = *(const float4*)(z + (n0 + rbase + fr) * 16 + q * 4);
                zhi[q] = *(const float4*)(z + (n0 + rbase + fr + 8) * 16 + q * 4);
            }
#pragma unroll
            for (int nt = 0; nt < 8; ++nt) {
                const int c0 = nq + nt * 8 + 2 * fc;
                float fb0 = __half2float(fb1h[c0]), fb1v = __half2float(fb1h[c0 + 1]);
                float f00 = fb0, f01 = fb1v, f10 = fb0, f11 = fb1v;
#pragma unroll
                for (int d = 0; d < 16; ++d) {
                    float2 wv = *(const float2*)(smF + O_WF / 4 + d * 256 + c0);
                    float zl = ((const float*)&zlo[d >> 2])[d & 3];
                    float zh = ((const float*)&zhi[d >> 2])[d & 3];
                    f00 = fmaf(zl, wv.x, f00); f01 = fmaf(zl, wv.y, f01);
                    f10 = fmaf(zh, wv.x, f10); f11 = fmaf(zh, wv.y, f11);
                }
                const float hb0 = __half2float(hb2h[c0]), hb1v = __half2float(hb2h[c0 + 1]);
                const int kkc = wcol * 4 + (nt >> 1);
                const int sbase = (nt & 1) * 2;
                {
                    float t2a = fast_tanh(acc[mt][nt][0] + hb0);
                    float t2b = fast_tanh(acc[mt][nt][1] + hb1v);
                    float g0 = 0.5f * (f00 * (1.0f - t2a * t2a)) + 0.5f * fast_tanh(f00);
                    float g1 = 0.5f * (f01 * (1.0f - t2b * t2b)) + 0.5f * fast_tanh(f01);
                    smU[O_SA / 4 + ((strip * 16 + kkc) * 32 + lane) * 4 + sbase] = h2u(g0, g1);
                }
                {
                    float t2a = fast_tanh(acc[mt][nt][2] + hb0);
                    float t2b = fast_tanh(acc[mt][nt][3] + hb1v);
                    float g0 = 0.5f * (f10 * (1.0f - t2a * t2a)) + 0.5f * fast_tanh(f10);
                    float g1 = 0.5f * (f11 * (1.0f - t2b * t2b)) + 0.5f * fast_tanh(f11);
                    smU[O_SA / 4 + ((strip * 16 + kkc) * 32 + lane) * 4 + sbase + 1] = h2u(g0, g1);
                }
            }
        }
    }
    __syncthreads();

    // ---------------- GEMM3: f2 = g @ fW2^T (B from L2) ----------------
#pragma unroll
    for (int mt = 0; mt < 2; ++mt)
#pragma unroll
        for (int nt = 0; nt < 8; ++nt)
#pragma unroll
            for (int i = 0; i < 4; ++i) acc[mt][nt][i] = 0.0f;
    gemm_big(sa4, g_wpk + 32768, wrow, wcol, lane, acc);
    __syncthreads();

    // ---------------- epi3 (register): h = .5*f2*s1 + .5*tanh(f2) -> sA ----------------
    {
        const __half* fb2h = (const __half*)(smx + O_FB2);
#pragma unroll
        for (int mt = 0; mt < 2; ++mt) {
            const int rbase = wrow * 32 + mt * 16;
            const int strip = wrow * 2 + mt;
            float4 zlo[4], zhi[4];
#pragma unroll
            for (int q = 0; q < 4; ++q) {
                zlo[q] = *(const float4*)(z + (n0 + rbase + fr) * 16 + q * 4);
                zhi[q] = *(const float4*)(z + (n0 + rbase + fr + 8) * 16 + q * 4);
            }
#pragma unroll
            for (int nt = 0; nt < 8; ++nt) {
                const int c0 = nq + nt * 8 + 2 * fc;
                float ab0 = smF[O_HB1 / 4 + c0], ab1 = smF[O_HB1 / 4 + c0 + 1];
                float a00 = ab0, a01 = ab1, a10 = ab0, a11 = ab1;   // a1 matvec
#pragma unroll
                for (int d = 0; d < 16; ++d) {
                    float2 wv = *(const float2*)(smF + O_WH / 4 + d * 256 + c0);
                    float zl = ((const float*)&zlo[d >> 2])[d & 3];
                    float zh = ((const float*)&zhi[d >> 2])[d & 3];
                    a00 = fmaf(zl, wv.x, a00); a01 = fmaf(zl, wv.y, a01);
                    a10 = fmaf(zh, wv.x, a10); a11 = fmaf(zh, wv.y, a11);
                }
                const float b0 = __half2float(fb2h[c0]), b1 = __half2float(fb2h[c0 + 1]);
                const int kkc = wcol * 4 + (nt >> 1);
                const int sbase = (nt & 1) * 2;
                {
                    float t1a = fast_tanh(a00), t1b = fast_tanh(a01);
                    float x0 = acc[mt][nt][0] + b0, x1 = acc[mt][nt][1] + b1;
                    float h0 = 0.5f * (x0 * (1.0f - t1a * t1a)) + 0.5f * fast_tanh(x0);
                    float h1 = 0.5f * (x1 * (1.0f - t1b * t1b)) + 0.5f * fast_tanh(x1);
                    smU[O_SA / 4 + ((strip * 16 + kkc) * 32 + lane) * 4 + sbase] = h2u(h0, h1);
                }
                {
                    float t1a = fast_tanh(a10), t1b = fast_tanh(a11);
                    float x0 = acc[mt][nt][2] + b0, x1 = acc[mt][nt][3] + b1;
                    float h0 = 0.5f * (x0 * (1.0f - t1a * t1a)) + 0.5f * fast_tanh(x0);
                    float h1 = 0.5f * (x1 * (1.0f - t1b * t1b)) + 0.5f * fast_tanh(x1);
                    smU[O_SA / 4 + ((strip * 16 + kkc) * 32 + lane) * 4 + sbase + 1] = h2u(h0, h1);
                }
            }
        }
    }
    __syncthreads();

    // ---------------- GEMM4: o = h @ fW3^T ; symplectic swap -> out ----------------
    {
        const int mstrip = w >> 1, nf4 = w & 1;
        const uint2* wf3 = (const uint2*)(smx + O_W3);
        float o[4] = {0.0f, 0.0f, 0.0f, 0.0f};
#pragma unroll
        for (int kk = 0; kk < 16; ++kk) {
            uint4 A = sa4[(mstrip * 16 + kk) * 32 + lane];
            uint2 B = wf3[(kk * 2 + nf4) * 32 + lane];
            mma16816(o, A.x, A.y, A.z, A.w, B.x, B.y);
        }
        const int j0 = nf4 * 8 + 2 * fc;
        const int dst = (j0 + 8) & 15;
        const float sgn = (j0 < 8) ? -1.0f : 1.0f;
        const float b0 = smF[O_FB3 / 4 + j0], b1 = smF[O_FB3 / 4 + j0 + 1];
        const long rlo = n0 + mstrip * 16 + fr;
        *(float2*)(out + rlo * 16 + dst)       = make_float2(sgn * (o[0] + b0), sgn * (o[1] + b1));
        *(float2*)(out + (rlo + 8) * 16 + dst) = make_float2(sgn * (o[2] + b0), sgn * (o[3] + b1));
    }
}

extern "C" void kernel_launch(void* const* d_in, const int* in_sizes, int n_in,
                              void* d_out, int out_size)
{
    // metadata order: t, z, hW1, hb1, hW2, hb2, fW1, fb1, fW2, fb2, fW3, fb3
    const float* z   = (const float*)d_in[1];
    const float* hW1 = (const float*)d_in[2];
    const float* hb1 = (const float*)d_in[3];
    const float* hW2 = (const float*)d_in[4];
    const float* hb2 = (const float*)d_in[5];
    const float* fW1 = (const float*)d_in[6];
    const float* fb1 = (const float*)d_in[7];
    const float* fW2 = (const float*)d_in[8];
    const float* fb2 = (const float*)d_in[9];
    const float* fW3 = (const float*)d_in[10];
    const float* fb3 = (const float*)d_in[11];
    float* out = (float*)d_out;

    const int n = in_sizes[1] / 16;          // 131072 rows
    const int grid = n / BM;                 // 2048 CTAs

    prepack<<<132, 512>>>(hW2, fW2, fW3);

    cudaFuncSetAttribute(flexhnn_f16,
                         cudaFuncAttributeMaxDynamicSharedMemorySize, SMEMB);
    flexhnn_f16<<<grid, NT, SMEMB>>>(z, hW1, hb1, hb2, fW1, fb1, fb2, fb3, out);
}

// round 8
// speedup vs baseline: 5.6236x; 5.6236x over previous
#include <cuda_runtime.h>
#include <cuda_fp16.h>
#include <cstdint>

#define NT 256
#define BM 64

// fp16 fragment-packed weights, written by prepack:
// [0,32768)     hW2 frags: ((kk*32+nf)*32+lane)*2+br
// [32768,65536) fW2 frags
// [65536,67584) fW3 frags: ((kk*2+nf)*32+lane)*2+br
// [67584,69632) hW1 frags: (nf*32+lane)*2+br   (K=16, single kk)
// [69632,71680) fW1 frags
__device__ __align__(16) uint32_t g_wpk[71680];

// ---- smem byte offsets ----
#define O_SA   0u        // 32KB: t1 frags -> h frags (canonical A-frag layout)
#define O_SB   32768u    // 32KB: f frags -> g frags
#define O_RING 65536u    // 4 x 8KB cp.async ring
#define O_HB1  98304u    // f32[256]
#define O_FB1  99328u
#define O_HB2  100352u
#define O_FB2  101376u
#define O_FB3  102400u   // f32[16]
#define SMEMB  102464

#define CP_ASYNC16(d, s) \
    asm volatile("cp.async.cg.shared.global [%0], [%1], 16;" :: "r"(d), "l"(s))
#define CP_COMMIT() asm volatile("cp.async.commit_group;" ::: "memory")
#define CP_WAIT2()  asm volatile("cp.async.wait_group 2;" ::: "memory")

__device__ __forceinline__ uint32_t smem_u32(const void* p) {
    uint32_t a;
    asm("{ .reg .u64 t; cvta.to.shared.u64 t, %1; cvt.u32.u64 %0, t; }" : "=r"(a) : "l"(p));
    return a;
}
__device__ __forceinline__ float fast_tanh(float x) {
    float e = __expf(2.0f * x);
    return 1.0f - __fdividef(2.0f, e + 1.0f);
}
__device__ __forceinline__ uint32_t h2u(float lo, float hi) {
    uint32_t r;
    asm("{ .reg .b16 l, h; cvt.rn.f16.f32 l, %1; cvt.rn.f16.f32 h, %2; mov.b32 %0, {l, h}; }"
        : "=r"(r) : "f"(lo), "f"(hi));
    return r;
}
__device__ __forceinline__ float2 uh2(uint32_t u) {
    __half2 h = *(__half2*)&u;
    return __half22float2(h);
}
__device__ __forceinline__ void mma16816(float d[4],
    uint32_t a0, uint32_t a1, uint32_t a2, uint32_t a3, uint32_t b0, uint32_t b1) {
    asm volatile("mma.sync.aligned.m16n8k16.row.col.f32.f16.f16.f32 "
                 "{%0,%1,%2,%3},{%4,%5,%6,%7},{%8,%9},{%0,%1,%2,%3};"
                 : "+f"(d[0]), "+f"(d[1]), "+f"(d[2]), "+f"(d[3])
                 : "r"(a0), "r"(a1), "r"(a2), "r"(a3), "r"(b0), "r"(b1));
}

// ---------- prepack ----------
__global__ void __launch_bounds__(512) prepack(const float* __restrict__ hW2,
                                               const float* __restrict__ fW2,
                                               const float* __restrict__ fW3,
                                               const float* __restrict__ hW1,
                                               const float* __restrict__ fW1) {
    int tid = blockIdx.x * 512 + threadIdx.x;
    if (tid < 65536) {
        int off = tid & 32767;
        const float* W = (tid >> 15) ? fW2 : hW2;
        int br = off & 1, lane = (off >> 1) & 31, nf = (off >> 6) & 31, kk = off >> 11;
        int n = nf * 8 + (lane >> 2), k = kk * 16 + 2 * (lane & 3) + br * 8;
        g_wpk[tid] = h2u(W[n * 256 + k], W[n * 256 + k + 1]);
    } else if (tid < 67584) {
        int off = tid - 65536;
        int br = off & 1, lane = (off >> 1) & 31, nf = (off >> 6) & 1, kk = off >> 7;
        int n = nf * 8 + (lane >> 2), k = kk * 16 + 2 * (lane & 3) + br * 8;
        g_wpk[tid] = h2u(fW3[n * 256 + k], fW3[n * 256 + k + 1]);
    } else if (tid < 71680) {
        int off = tid - 67584;
        const float* W = (off >= 2048) ? fW1 : hW1;
        off &= 2047;
        int br = off & 1, lane = (off >> 1) & 31, nf = off >> 6;
        int n = nf * 8 + (lane >> 2), k = 2 * (lane & 3) + br * 8;
        g_wpk[tid] = h2u(W[n * 16 + k], W[n * 16 + k + 1]);
    }
}

__device__ __forceinline__ void ring_issue(uint32_t ringb, const uint32_t* wsrc, int c, int t) {
    if (c < 16) {
        uint32_t dst = ringb + (uint32_t)(((c & 3) << 13) + (t << 5));
        const char* src = (const char*)(wsrc + (c << 11)) + (t << 5);
        CP_ASYNC16(dst, src);
        CP_ASYNC16(dst + 16, src + 16);
    }
    CP_COMMIT();
}

#define ZERO_ACC(acc) do { \
    _Pragma("unroll") for (int _m = 0; _m < 2; ++_m) \
    _Pragma("unroll") for (int _n = 0; _n < 8; ++_n) \
    _Pragma("unroll") for (int _i = 0; _i < 4; ++_i) (acc)[_m][_n][_i] = 0.0f; \
} while (0)

// Big GEMM: A frags from ab (smem), B streamed from wsrc via ring.
// Prologue (chunks 0..2) must already be issued. Ends with __syncthreads().
__device__ __forceinline__ void gemm_ring(const uint4* __restrict__ ab, const char* smx,
                                          uint32_t ringb, const uint32_t* __restrict__ wsrc,
                                          int wrow, int wcol, int lane, int t,
                                          float acc[2][8][4]) {
    const int s0 = wrow * 2;
#pragma unroll
    for (int kk = 0; kk < 16; ++kk) {
        CP_WAIT2();
        __syncthreads();
        ring_issue(ringb, wsrc, kk + 3, t);
        const uint32_t* rb = (const uint32_t*)(smx + O_RING + ((kk & 3) << 13));
        uint4 A0 = ab[(s0 * 16 + kk) * 32 + lane];
        uint4 A1 = ab[((s0 + 1) * 16 + kk) * 32 + lane];
        uint2 B[8];
#pragma unroll
        for (int nt = 0; nt < 8; ++nt)
            B[nt] = *(const uint2*)(rb + (((wcol << 3) + nt) * 32 + lane) * 2);
#pragma unroll
        for (int nt = 0; nt < 8; ++nt) {
            mma16816(acc[0][nt], A0.x, A0.y, A0.z, A0.w, B[nt].x, B[nt].y);
            mma16816(acc[1][nt], A1.x, A1.y, A1.z, A1.w, B[nt].x, B[nt].y);
        }
    }
    __syncthreads();   // all ring reads done before caller reuses slots
}

__global__ void __launch_bounds__(NT, 2)
flexhnn_f16(const float* __restrict__ z,
            const float* __restrict__ hb1, const float* __restrict__ hb2,
            const float* __restrict__ fb1, const float* __restrict__ fb2,
            const float* __restrict__ fb3,
            float* __restrict__ out)
{
    extern __shared__ __align__(16) char smx[];
    float* smF = (float*)smx;
    uint4* sa4 = (uint4*)(smx + O_SA);
    uint4* sb4 = (uint4*)(smx + O_SB);
    const uint32_t ringb = smem_u32(smx) + O_RING;

    const int t = threadIdx.x, lane = t & 31, w = t >> 5;
    const int fr = lane >> 2, fc = lane & 3;
    const int wrow = w & 1, wcol = w >> 1;     // 8 warps: 2 row-halves x 4 col-quarters
    const long n0 = (long)blockIdx.x * BM;

    // ---- stage biases ----
    smF[O_HB1 / 4 + t] = hb1[t];
    smF[O_FB1 / 4 + t] = fb1[t];
    smF[O_HB2 / 4 + t] = hb2[t];
    smF[O_FB2 / 4 + t] = fb2[t];
    if (t < 16) smF[O_FB3 / 4 + t] = fb3[t];
    __syncthreads();

    // ---- GEMM1: z A-frags (fp16) ----
    uint4 Az[2];
#pragma unroll
    for (int mt = 0; mt < 2; ++mt) {
        const long rl = n0 + (wrow * 32 + mt * 16 + fr);
        float2 zl0 = *(const float2*)(z + rl * 16 + 2 * fc);
        float2 zl8 = *(const float2*)(z + rl * 16 + 2 * fc + 8);
        float2 zh0 = *(const float2*)(z + (rl + 8) * 16 + 2 * fc);
        float2 zh8 = *(const float2*)(z + (rl + 8) * 16 + 2 * fc + 8);
        Az[mt].x = h2u(zl0.x, zl0.y); Az[mt].y = h2u(zh0.x, zh0.y);
        Az[mt].z = h2u(zl8.x, zl8.y); Az[mt].w = h2u(zh8.x, zh8.y);
    }

    float acc[2][8][4];

    // ---- GEMM1a: a1 = z @ hW1^T ; epi1a: t1 -> SA frags ----
    ZERO_ACC(acc);
#pragma unroll
    for (int nt = 0; nt < 8; ++nt) {
        uint2 B = *(const uint2*)(g_wpk + 67584 + (((wcol << 3) + nt) * 32 + lane) * 2);
        mma16816(acc[0][nt], Az[0].x, Az[0].y, Az[0].z, Az[0].w, B.x, B.y);
        mma16816(acc[1][nt], Az[1].x, Az[1].y, Az[1].z, Az[1].w, B.x, B.y);
    }
#pragma unroll
    for (int mt = 0; mt < 2; ++mt) {
        const int strip = wrow * 2 + mt;
#pragma unroll
        for (int j = 0; j < 4; ++j) {
            const int kkc = wcol * 4 + j;
            const int c0 = (wcol << 6) + (j << 4) + 2 * fc;
            float2 bA = *(const float2*)(smF + O_HB1 / 4 + c0);
            float2 bB = *(const float2*)(smF + O_HB1 / 4 + c0 + 8);
            uint4 v;
            v.x = h2u(fast_tanh(acc[mt][2*j][0] + bA.x), fast_tanh(acc[mt][2*j][1] + bA.y));
            v.y = h2u(fast_tanh(acc[mt][2*j][2] + bA.x), fast_tanh(acc[mt][2*j][3] + bA.y));
            v.z = h2u(fast_tanh(acc[mt][2*j+1][0] + bB.x), fast_tanh(acc[mt][2*j+1][1] + bB.y));
            v.w = h2u(fast_tanh(acc[mt][2*j+1][2] + bB.x), fast_tanh(acc[mt][2*j+1][3] + bB.y));
            sa4[(strip * 16 + kkc) * 32 + lane] = v;
        }
    }

    // ---- GEMM1b: f = z @ fW1^T + fb1 ; epi1b: f -> SB frags ----
    ZERO_ACC(acc);
#pragma unroll
    for (int nt = 0; nt < 8; ++nt) {
        uint2 B = *(const uint2*)(g_wpk + 69632 + (((wcol << 3) + nt) * 32 + lane) * 2);
        mma16816(acc[0][nt], Az[0].x, Az[0].y, Az[0].z, Az[0].w, B.x, B.y);
        mma16816(acc[1][nt], Az[1].x, Az[1].y, Az[1].z, Az[1].w, B.x, B.y);
    }
#pragma unroll
    for (int mt = 0; mt < 2; ++mt) {
        const int strip = wrow * 2 + mt;
#pragma unroll
        for (int j = 0; j < 4; ++j) {
            const int kkc = wcol * 4 + j;
            const int c0 = (wcol << 6) + (j << 4) + 2 * fc;
            float2 bA = *(const float2*)(smF + O_FB1 / 4 + c0);
            float2 bB = *(const float2*)(smF + O_FB1 / 4 + c0 + 8);
            uint4 v;
            v.x = h2u(acc[mt][2*j][0] + bA.x, acc[mt][2*j][1] + bA.y);
            v.y = h2u(acc[mt][2*j][2] + bA.x, acc[mt][2*j][3] + bA.y);
            v.z = h2u(acc[mt][2*j+1][0] + bB.x, acc[mt][2*j+1][1] + bB.y);
            v.w = h2u(acc[mt][2*j+1][2] + bB.x, acc[mt][2*j+1][3] + bB.y);
            sb4[(strip * 16 + kkc) * 32 + lane] = v;
        }
    }

    // prologue for GEMM2 ring (hW2), then make SA/SB visible
    ring_issue(ringb, g_wpk, 0, t);
    ring_issue(ringb, g_wpk, 1, t);
    ring_issue(ringb, g_wpk, 2, t);
    __syncthreads();

    // ---- GEMM2: a2 = t1 @ hW2^T ----
    ZERO_ACC(acc);
    gemm_ring(sa4, smx, ringb, g_wpk, wrow, wcol, lane, t, acc);

    // prologue for GEMM3 ring (fW2) — overlaps epi2
    ring_issue(ringb, g_wpk + 32768, 0, t);
    ring_issue(ringb, g_wpk + 32768, 1, t);
    ring_issue(ringb, g_wpk + 32768, 2, t);

    // ---- epi2: g = .5*f*s2 + .5*tanh(f)  (f from SB, overwrite with g) ----
#pragma unroll
    for (int mt = 0; mt < 2; ++mt) {
        const int strip = wrow * 2 + mt;
#pragma unroll
        for (int j = 0; j < 4; ++j) {
            const int kkc = wcol * 4 + j;
            const int c0 = (wcol << 6) + (j << 4) + 2 * fc;
            uint4* p = sb4 + (strip * 16 + kkc) * 32 + lane;
            uint4 fv = *p;
            float2 bA = *(const float2*)(smF + O_HB2 / 4 + c0);
            float2 bB = *(const float2*)(smF + O_HB2 / 4 + c0 + 8);
            float2 flo = uh2(fv.x), fhi = uh2(fv.y), glo = uh2(fv.z), ghi = uh2(fv.w);
            float t2, s2, fx;
            uint4 o;
            #define MIX(av, bb, ff) (t2 = fast_tanh((av) + (bb)), s2 = 1.0f - t2 * t2, \
                                     fx = (ff), 0.5f * (fx * s2) + 0.5f * fast_tanh(fx))
            o.x = h2u(MIX(acc[mt][2*j][0], bA.x, flo.x), MIX(acc[mt][2*j][1], bA.y, flo.y));
            o.y = h2u(MIX(acc[mt][2*j][2], bA.x, fhi.x), MIX(acc[mt][2*j][3], bA.y, fhi.y));
            o.z = h2u(MIX(acc[mt][2*j+1][0], bB.x, glo.x), MIX(acc[mt][2*j+1][1], bB.y, glo.y));
            o.w = h2u(MIX(acc[mt][2*j+1][2], bB.x, ghi.x), MIX(acc[mt][2*j+1][3], bB.y, ghi.y));
            #undef MIX
            *p = o;
        }
    }
    __syncthreads();

    // ---- GEMM3: f2 = g @ fW2^T ----
    ZERO_ACC(acc);
    gemm_ring(sb4, smx, ringb, g_wpk + 32768, wrow, wcol, lane, t, acc);

    // ---- epi3: h = .5*f2*s1 + .5*tanh(f2), s1 = 1 - t1^2 (t1 from SA, overwrite with h) ----
#pragma unroll
    for (int mt = 0; mt < 2; ++mt) {
        const int strip = wrow * 2 + mt;
#pragma unroll
        for (int j = 0; j < 4; ++j) {
            const int kkc = wcol * 4 + j;
            const int c0 = (wcol << 6) + (j << 4) + 2 * fc;
            uint4* p = sa4 + (strip * 16 + kkc) * 32 + lane;
            uint4 tv = *p;
            float2 bA = *(const float2*)(smF + O_FB2 / 4 + c0);
            float2 bB = *(const float2*)(smF + O_FB2 / 4 + c0 + 8);
            float2 tlo = uh2(tv.x), thi = uh2(tv.y), ulo = uh2(tv.z), uhi = uh2(tv.w);
            float f2, s1;
            uint4 o;
            #define HMX(av, bb, tt) (f2 = (av) + (bb), s1 = 1.0f - (tt) * (tt), \
                                     0.5f * (f2 * s1) + 0.5f * fast_tanh(f2))
            o.x = h2u(HMX(acc[mt][2*j][0], bA.x, tlo.x), HMX(acc[mt][2*j][1], bA.y, tlo.y));
            o.y = h2u(HMX(acc[mt][2*j][2], bA.x, thi.x), HMX(acc[mt][2*j][3], bA.y, thi.y));
            o.z = h2u(HMX(acc[mt][2*j+1][0], bB.x, ulo.x), HMX(acc[mt][2*j+1][1], bB.y, ulo.y));
            o.w = h2u(HMX(acc[mt][2*j+1][2], bB.x, uhi.x), HMX(acc[mt][2*j+1][3], bB.y, uhi.y));
            #undef HMX
            *p = o;
        }
    }
    __syncthreads();

    // ---- GEMM4: o = h @ fW3^T ; symplectic swap -> out ----
    {
        const int strip = w >> 1, nf4 = w & 1;
        uint2 B[16];
#pragma unroll
        for (int kk = 0; kk < 16; ++kk)
            B[kk] = *(const uint2*)(g_wpk + 65536 + (((kk * 2 + nf4) * 32 + lane) * 2));
        float o[4] = {0.0f, 0.0f, 0.0f, 0.0f};
#pragma unroll
        for (int kk = 0; kk < 16; ++kk) {
            uint4 A = sa4[(strip * 16 + kk) * 32 + lane];
            mma16816(o, A.x, A.y, A.z, A.w, B[kk].x, B[kk].y);
        }
        const int j0 = nf4 * 8 + 2 * fc;
        const int dst = (j0 + 8) & 15;
        const float sgn = (j0 < 8) ? -1.0f : 1.0f;
        const float b0 = smF[O_FB3 / 4 + j0], b1 = smF[O_FB3 / 4 + j0 + 1];
        const long rlo = n0 + strip * 16 + fr;
        *(float2*)(out + rlo * 16 + dst)       = make_float2(sgn * (o[0] + b0), sgn * (o[1] + b1));
        *(float2*)(out + (rlo + 8) * 16 + dst) = make_float2(sgn * (o[2] + b0), sgn * (o[3] + b1));
    }
}

extern "C" void kernel_launch(void* const* d_in, const int* in_sizes, int n_in,
                              void* d_out, int out_size)
{
    // metadata order: t, z, hW1, hb1, hW2, hb2, fW1, fb1, fW2, fb2, fW3, fb3
    const float* z   = (const float*)d_in[1];
    const float* hW1 = (const float*)d_in[2];
    const float* hb1 = (const float*)d_in[3];
    const float* hW2 = (const float*)d_in[4];
    const float* hb2 = (const float*)d_in[5];
    const float* fW1 = (const float*)d_in[6];
    const float* fb1 = (const float*)d_in[7];
    const float* fW2 = (const float*)d_in[8];
    const float* fb2 = (const float*)d_in[9];
    const float* fW3 = (const float*)d_in[10];
    const float* fb3 = (const float*)d_in[11];
    float* out = (float*)d_out;

    const int n = in_sizes[1] / 16;          // 131072 rows
    const int grid = n / BM;                 // 2048 CTAs

    prepack<<<140, 512>>>(hW2, fW2, fW3, hW1, fW1);

    cudaFuncSetAttribute(flexhnn_f16,
                         cudaFuncAttributeMaxDynamicSharedMemorySize, SMEMB);
    flexhnn_f16<<<grid, NT, SMEMB>>>(z, hb1, hb2, fb1, fb2, fb3, out);
}

// round 9
// speedup vs baseline: 6.8770x; 1.2229x over previous
#include <cuda_runtime.h>
#include <cuda_fp16.h>
#include <cstdint>

#define NT 256
#define BM 64

// fp16 fragment-packed weights, written by prepack:
// [0,32768)     hW2 frags: ((kk*32+nf)*32+lane)*2+br
// [32768,65536) fW2 frags
// [65536,67584) fW3 frags: ((kk*2+nf)*32+lane)*2+br
// [67584,69632) hW1 frags: (nf*32+lane)*2+br   (K=16, single kk)
// [69632,71680) fW1 frags
__device__ __align__(16) uint32_t g_wpk[71680];

// ---- smem byte offsets ----
#define O_SA   0u        // 32KB: t1 frags -> h frags (canonical A-frag layout)
#define O_SB   32768u    // 32KB: f frags -> g frags
#define O_RING 65536u    // 4 x 8KB cp.async ring
#define O_HB1  98304u    // f32[256]
#define O_FB1  99328u
#define O_HB2  100352u
#define O_FB2  101376u
#define O_FB3  102400u   // f32[16]
#define SMEMB  102464

#define CP_ASYNC16(d, s) \
    asm volatile("cp.async.cg.shared.global [%0], [%1], 16;" :: "r"(d), "l"(s))
#define CP_COMMIT() asm volatile("cp.async.commit_group;" ::: "memory")
#define CP_WAIT2()  asm volatile("cp.async.wait_group 2;" ::: "memory")

__device__ __forceinline__ uint32_t smem_u32(const void* p) {
    uint32_t a;
    asm("{ .reg .u64 t; cvta.to.shared.u64 t, %1; cvt.u32.u64 %0, t; }" : "=r"(a) : "l"(p));
    return a;
}
// hardware tanh: 1 MUFU op (vs EX2+RCP+4 ALU)
__device__ __forceinline__ float fast_tanh(float x) {
    float y;
    asm("tanh.approx.f32 %0, %1;" : "=f"(y) : "f"(x));
    return y;
}
__device__ __forceinline__ uint32_t h2u(float lo, float hi) {
    uint32_t r;
    asm("{ .reg .b16 l, h; cvt.rn.f16.f32 l, %1; cvt.rn.f16.f32 h, %2; mov.b32 %0, {l, h}; }"
        : "=r"(r) : "f"(lo), "f"(hi));
    return r;
}
__device__ __forceinline__ float2 uh2(uint32_t u) {
    __half2 h = *(__half2*)&u;
    return __half22float2(h);
}
__device__ __forceinline__ void mma16816(float d[4],
    uint32_t a0, uint32_t a1, uint32_t a2, uint32_t a3, uint32_t b0, uint32_t b1) {
    asm volatile("mma.sync.aligned.m16n8k16.row.col.f32.f16.f16.f32 "
                 "{%0,%1,%2,%3},{%4,%5,%6,%7},{%8,%9},{%0,%1,%2,%3};"
                 : "+f"(d[0]), "+f"(d[1]), "+f"(d[2]), "+f"(d[3])
                 : "r"(a0), "r"(a1), "r"(a2), "r"(a3), "r"(b0), "r"(b1));
}

// ---------- prepack ----------
__global__ void __launch_bounds__(512) prepack(const float* __restrict__ hW2,
                                               const float* __restrict__ fW2,
                                               const float* __restrict__ fW3,
                                               const float* __restrict__ hW1,
                                               const float* __restrict__ fW1) {
    int tid = blockIdx.x * 512 + threadIdx.x;
    if (tid < 65536) {
        int off = tid & 32767;
        const float* W = (tid >> 15) ? fW2 : hW2;
        int br = off & 1, lane = (off >> 1) & 31, nf = (off >> 6) & 31, kk = off >> 11;
        int n = nf * 8 + (lane >> 2), k = kk * 16 + 2 * (lane & 3) + br * 8;
        g_wpk[tid] = h2u(W[n * 256 + k], W[n * 256 + k + 1]);
    } else if (tid < 67584) {
        int off = tid - 65536;
        int br = off & 1, lane = (off >> 1) & 31, nf = (off >> 6) & 1, kk = off >> 7;
        int n = nf * 8 + (lane >> 2), k = kk * 16 + 2 * (lane & 3) + br * 8;
        g_wpk[tid] = h2u(fW3[n * 256 + k], fW3[n * 256 + k + 1]);
    } else if (tid < 71680) {
        int off = tid - 67584;
        const float* W = (off >= 2048) ? fW1 : hW1;
        off &= 2047;
        int br = off & 1, lane = (off >> 1) & 31, nf = off >> 6;
        int n = nf * 8 + (lane >> 2), k = 2 * (lane & 3) + br * 8;
        g_wpk[tid] = h2u(W[n * 16 + k], W[n * 16 + k + 1]);
    }
}

__device__ __forceinline__ void ring_issue(uint32_t ringb, const uint32_t* wsrc, int c, int t) {
    if (c < 16) {
        uint32_t dst = ringb + (uint32_t)(((c & 3) << 13) + (t << 5));
        const char* src = (const char*)(wsrc + (c << 11)) + (t << 5);
        CP_ASYNC16(dst, src);
        CP_ASYNC16(dst + 16, src + 16);
    }
    CP_COMMIT();
}

#define ZERO_ACC(acc) do { \
    _Pragma("unroll") for (int _m = 0; _m < 2; ++_m) \
    _Pragma("unroll") for (int _n = 0; _n < 8; ++_n) \
    _Pragma("unroll") for (int _i = 0; _i < 4; ++_i) (acc)[_m][_n][_i] = 0.0f; \
} while (0)

// Big GEMM: A frags from ab (smem), B streamed from wsrc via ring.
// Prologue (chunks 0..2) must already be issued. Ends with __syncthreads().
__device__ __forceinline__ void gemm_ring(const uint4* __restrict__ ab, const char* smx,
                                          uint32_t ringb, const uint32_t* __restrict__ wsrc,
                                          int wrow, int wcol, int lane, int t,
                                          float acc[2][8][4]) {
    const int s0 = wrow * 2;
#pragma unroll
    for (int kk = 0; kk < 16; ++kk) {
        CP_WAIT2();
        __syncthreads();
        ring_issue(ringb, wsrc, kk + 3, t);
        const uint32_t* rb = (const uint32_t*)(smx + O_RING + ((kk & 3) << 13));
        uint4 A0 = ab[(s0 * 16 + kk) * 32 + lane];
        uint4 A1 = ab[((s0 + 1) * 16 + kk) * 32 + lane];
        uint2 B[8];
#pragma unroll
        for (int nt = 0; nt < 8; ++nt)
            B[nt] = *(const uint2*)(rb + (((wcol << 3) + nt) * 32 + lane) * 2);
#pragma unroll
        for (int nt = 0; nt < 8; ++nt) {
            mma16816(acc[0][nt], A0.x, A0.y, A0.z, A0.w, B[nt].x, B[nt].y);
            mma16816(acc[1][nt], A1.x, A1.y, A1.z, A1.w, B[nt].x, B[nt].y);
        }
    }
    __syncthreads();   // all ring reads done before caller reuses slots
}

__global__ void __launch_bounds__(NT, 2)
flexhnn_f16(const float* __restrict__ z,
            const float* __restrict__ hb1, const float* __restrict__ hb2,
            const float* __restrict__ fb1, const float* __restrict__ fb2,
            const float* __restrict__ fb3,
            float* __restrict__ out)
{
    extern __shared__ __align__(16) char smx[];
    float* smF = (float*)smx;
    uint4* sa4 = (uint4*)(smx + O_SA);
    uint4* sb4 = (uint4*)(smx + O_SB);
    const uint32_t ringb = smem_u32(smx) + O_RING;

    const int t = threadIdx.x, lane = t & 31, w = t >> 5;
    const int fr = lane >> 2, fc = lane & 3;
    const int wrow = w & 1, wcol = w >> 1;     // 8 warps: 2 row-halves x 4 col-quarters
    const long n0 = (long)blockIdx.x * BM;

    // ---- stage biases ----
    smF[O_HB1 / 4 + t] = hb1[t];
    smF[O_FB1 / 4 + t] = fb1[t];
    smF[O_HB2 / 4 + t] = hb2[t];
    smF[O_FB2 / 4 + t] = fb2[t];
    if (t < 16) smF[O_FB3 / 4 + t] = fb3[t];
    __syncthreads();

    // ---- GEMM1: z A-frags (fp16) ----
    uint4 Az[2];
#pragma unroll
    for (int mt = 0; mt < 2; ++mt) {
        const long rl = n0 + (wrow * 32 + mt * 16 + fr);
        float2 zl0 = *(const float2*)(z + rl * 16 + 2 * fc);
        float2 zl8 = *(const float2*)(z + rl * 16 + 2 * fc + 8);
        float2 zh0 = *(const float2*)(z + (rl + 8) * 16 + 2 * fc);
        float2 zh8 = *(const float2*)(z + (rl + 8) * 16 + 2 * fc + 8);
        Az[mt].x = h2u(zl0.x, zl0.y); Az[mt].y = h2u(zh0.x, zh0.y);
        Az[mt].z = h2u(zl8.x, zl8.y); Az[mt].w = h2u(zh8.x, zh8.y);
    }

    float acc[2][8][4];

    // ---- GEMM1a: a1 = z @ hW1^T ; epi1a: t1 -> SA frags ----
    ZERO_ACC(acc);
#pragma unroll
    for (int nt = 0; nt < 8; ++nt) {
        uint2 B = *(const uint2*)(g_wpk + 67584 + (((wcol << 3) + nt) * 32 + lane) * 2);
        mma16816(acc[0][nt], Az[0].x, Az[0].y, Az[0].z, Az[0].w, B.x, B.y);
        mma16816(acc[1][nt], Az[1].x, Az[1].y, Az[1].z, Az[1].w, B.x, B.y);
    }
#pragma unroll
    for (int mt = 0; mt < 2; ++mt) {
        const int strip = wrow * 2 + mt;
#pragma unroll
        for (int j = 0; j < 4; ++j) {
            const int kkc = wcol * 4 + j;
            const int c0 = (wcol << 6) + (j << 4) + 2 * fc;
            float2 bA = *(const float2*)(smF + O_HB1 / 4 + c0);
            float2 bB = *(const float2*)(smF + O_HB1 / 4 + c0 + 8);
            uint4 v;
            v.x = h2u(fast_tanh(acc[mt][2*j][0] + bA.x), fast_tanh(acc[mt][2*j][1] + bA.y));
            v.y = h2u(fast_tanh(acc[mt][2*j][2] + bA.x), fast_tanh(acc[mt][2*j][3] + bA.y));
            v.z = h2u(fast_tanh(acc[mt][2*j+1][0] + bB.x), fast_tanh(acc[mt][2*j+1][1] + bB.y));
            v.w = h2u(fast_tanh(acc[mt][2*j+1][2] + bB.x), fast_tanh(acc[mt][2*j+1][3] + bB.y));
            sa4[(strip * 16 + kkc) * 32 + lane] = v;
        }
    }

    // ---- GEMM1b: f = z @ fW1^T + fb1 ; epi1b: f -> SB frags ----
    ZERO_ACC(acc);
#pragma unroll
    for (int nt = 0; nt < 8; ++nt) {
        uint2 B = *(const uint2*)(g_wpk + 69632 + (((wcol << 3) + nt) * 32 + lane) * 2);
        mma16816(acc[0][nt], Az[0].x, Az[0].y, Az[0].z, Az[0].w, B.x, B.y);
        mma16816(acc[1][nt], Az[1].x, Az[1].y, Az[1].z, Az[1].w, B.x, B.y);
    }
#pragma unroll
    for (int mt = 0; mt < 2; ++mt) {
        const int strip = wrow * 2 + mt;
#pragma unroll
        for (int j = 0; j < 4; ++j) {
            const int kkc = wcol * 4 + j;
            const int c0 = (wcol << 6) + (j << 4) + 2 * fc;
            float2 bA = *(const float2*)(smF + O_FB1 / 4 + c0);
            float2 bB = *(const float2*)(smF + O_FB1 / 4 + c0 + 8);
            uint4 v;
            v.x = h2u(acc[mt][2*j][0] + bA.x, acc[mt][2*j][1] + bA.y);
            v.y = h2u(acc[mt][2*j][2] + bA.x, acc[mt][2*j][3] + bA.y);
            v.z = h2u(acc[mt][2*j+1][0] + bB.x, acc[mt][2*j+1][1] + bB.y);
            v.w = h2u(acc[mt][2*j+1][2] + bB.x, acc[mt][2*j+1][3] + bB.y);
            sb4[(strip * 16 + kkc) * 32 + lane] = v;
        }
    }

    // prologue for GEMM2 ring (hW2), then make SA/SB visible
    ring_issue(ringb, g_wpk, 0, t);
    ring_issue(ringb, g_wpk, 1, t);
    ring_issue(ringb, g_wpk, 2, t);
    __syncthreads();

    // ---- GEMM2: a2 = t1 @ hW2^T ----
    ZERO_ACC(acc);
    gemm_ring(sa4, smx, ringb, g_wpk, wrow, wcol, lane, t, acc);

    // prologue for GEMM3 ring (fW2) — overlaps epi2
    ring_issue(ringb, g_wpk + 32768, 0, t);
    ring_issue(ringb, g_wpk + 32768, 1, t);
    ring_issue(ringb, g_wpk + 32768, 2, t);

    // ---- epi2: g = .5*f*s2 + .5*tanh(f)  (f from SB, overwrite with g) ----
#pragma unroll
    for (int mt = 0; mt < 2; ++mt) {
        const int strip = wrow * 2 + mt;
#pragma unroll
        for (int j = 0; j < 4; ++j) {
            const int kkc = wcol * 4 + j;
            const int c0 = (wcol << 6) + (j << 4) + 2 * fc;
            uint4* p = sb4 + (strip * 16 + kkc) * 32 + lane;
            uint4 fv = *p;
            float2 bA = *(const float2*)(smF + O_HB2 / 4 + c0);
            float2 bB = *(const float2*)(smF + O_HB2 / 4 + c0 + 8);
            float2 flo = uh2(fv.x), fhi = uh2(fv.y), glo = uh2(fv.z), ghi = uh2(fv.w);
            float t2, s2, fx;
            uint4 o;
            #define MIX(av, bb, ff) (t2 = fast_tanh((av) + (bb)), s2 = 1.0f - t2 * t2, \
                                     fx = (ff), 0.5f * (fx * s2) + 0.5f * fast_tanh(fx))
            o.x = h2u(MIX(acc[mt][2*j][0], bA.x, flo.x), MIX(acc[mt][2*j][1], bA.y, flo.y));
            o.y = h2u(MIX(acc[mt][2*j][2], bA.x, fhi.x), MIX(acc[mt][2*j][3], bA.y, fhi.y));
            o.z = h2u(MIX(acc[mt][2*j+1][0], bB.x, glo.x), MIX(acc[mt][2*j+1][1], bB.y, glo.y));
            o.w = h2u(MIX(acc[mt][2*j+1][2], bB.x, ghi.x), MIX(acc[mt][2*j+1][3], bB.y, ghi.y));
            #undef MIX
            *p = o;
        }
    }
    __syncthreads();

    // ---- GEMM3: f2 = g @ fW2^T ----
    ZERO_ACC(acc);
    gemm_ring(sb4, smx, ringb, g_wpk + 32768, wrow, wcol, lane, t, acc);

    // ---- epi3: h = .5*f2*s1 + .5*tanh(f2), s1 = 1 - t1^2 (t1 from SA, overwrite with h) ----
#pragma unroll
    for (int mt = 0; mt < 2; ++mt) {
        const int strip = wrow * 2 + mt;
#pragma unroll
        for (int j = 0; j < 4; ++j) {
            const int kkc = wcol * 4 + j;
            const int c0 = (wcol << 6) + (j << 4) + 2 * fc;
            uint4* p = sa4 + (strip * 16 + kkc) * 32 + lane;
            uint4 tv = *p;
            float2 bA = *(const float2*)(smF + O_FB2 / 4 + c0);
            float2 bB = *(const float2*)(smF + O_FB2 / 4 + c0 + 8);
            float2 tlo = uh2(tv.x), thi = uh2(tv.y), ulo = uh2(tv.z), uhi = uh2(tv.w);
            float f2, s1;
            uint4 o;
            #define HMX(av, bb, tt) (f2 = (av) + (bb), s1 = 1.0f - (tt) * (tt), \
                                     0.5f * (f2 * s1) + 0.5f * fast_tanh(f2))
            o.x = h2u(HMX(acc[mt][2*j][0], bA.x, tlo.x), HMX(acc[mt][2*j][1], bA.y, tlo.y));
            o.y = h2u(HMX(acc[mt][2*j][2], bA.x, thi.x), HMX(acc[mt][2*j][3], bA.y, thi.y));
            o.z = h2u(HMX(acc[mt][2*j+1][0], bB.x, ulo.x), HMX(acc[mt][2*j+1][1], bB.y, ulo.y));
            o.w = h2u(HMX(acc[mt][2*j+1][2], bB.x, uhi.x), HMX(acc[mt][2*j+1][3], bB.y, uhi.y));
            #undef HMX
            *p = o;
        }
    }
    __syncthreads();

    // ---- GEMM4: o = h @ fW3^T ; symplectic swap -> out ----
    {
        const int strip = w >> 1, nf4 = w & 1;
        uint2 B[16];
#pragma unroll
        for (int kk = 0; kk < 16; ++kk)
            B[kk] = *(const uint2*)(g_wpk + 65536 + (((kk * 2 + nf4) * 32 + lane) * 2));
        float o[4] = {0.0f, 0.0f, 0.0f, 0.0f};
#pragma unroll
        for (int kk = 0; kk < 16; ++kk) {
            uint4 A = sa4[(strip * 16 + kk) * 32 + lane];
            mma16816(o, A.x, A.y, A.z, A.w, B[kk].x, B[kk].y);
        }
        const int j0 = nf4 * 8 + 2 * fc;
        const int dst = (j0 + 8) & 15;
        const float sgn = (j0 < 8) ? -1.0f : 1.0f;
        const float b0 = smF[O_FB3 / 4 + j0], b1 = smF[O_FB3 / 4 + j0 + 1];
        const long rlo = n0 + strip * 16 + fr;
        *(float2*)(out + rlo * 16 + dst)       = make_float2(sgn * (o[0] + b0), sgn * (o[1] + b1));
        *(float2*)(out + (rlo + 8) * 16 + dst) = make_float2(sgn * (o[2] + b0), sgn * (o[3] + b1));
    }
}

extern "C" void kernel_launch(void* const* d_in, const int* in_sizes, int n_in,
                              void* d_out, int out_size)
{
    // metadata order: t, z, hW1, hb1, hW2, hb2, fW1, fb1, fW2, fb2, fW3, fb3
    const float* z   = (const float*)d_in[1];
    const float* hW1 = (const float*)d_in[2];
    const float* hb1 = (const float*)d_in[3];
    const float* hW2 = (const float*)d_in[4];
    const float* hb2 = (const float*)d_in[5];
    const float* fW1 = (const float*)d_in[6];
    const float* fb1 = (const float*)d_in[7];
    const float* fW2 = (const float*)d_in[8];
    const float* fb2 = (const float*)d_in[9];
    const float* fW3 = (const float*)d_in[10];
    const float* fb3 = (const float*)d_in[11];
    float* out = (float*)d_out;

    const int n = in_sizes[1] / 16;          // 131072 rows
    const int grid = n / BM;                 // 2048 CTAs

    prepack<<<140, 512>>>(hW2, fW2, fW3, hW1, fW1);

    cudaFuncSetAttribute(flexhnn_f16,
                         cudaFuncAttributeMaxDynamicSharedMemorySize, SMEMB);
    flexhnn_f16<<<grid, NT, SMEMB>>>(z, hb1, hb2, fb1, fb2, fb3, out);
}

// round 10
// speedup vs baseline: 7.2426x; 1.0532x over previous
#include <cuda_runtime.h>
#include <cuda_fp16.h>
#include <cstdint>

#define NT 256
#define BM 64

// fp16 fragment-packed weights, written by prepack:
// [0,32768)     hW2 frags, uint4-paired: ((kk*16+np)*32+lane)*4 + wd,
//               wd: nt=2np+(wd>>1), br=wd&1
// [32768,65536) fW2 frags (same layout)
// [65536,67584) fW3 frags: ((kk*2+nf)*32+lane)*2+br
// [67584,69632) hW1 frags: (nf*32+lane)*2+br   (K=16, single kk)
// [69632,71680) fW1 frags
__device__ __align__(16) uint32_t g_wpk[71680];

// ---- smem byte offsets ----
#define O_SA   0u        // 32KB: t1 frags -> h frags (canonical A-frag layout)
#define O_SB   32768u    // 32KB: f frags -> g frags
#define O_RING 65536u    // 4 x 8KB cp.async ring
#define O_HB1  98304u    // f32[256]
#define O_FB1  99328u
#define O_HB2  100352u
#define O_FB2  101376u
#define O_FB3  102400u   // f32[16]
#define SMEMB  102464

#define CP_ASYNC16(d, s) \
    asm volatile("cp.async.cg.shared.global [%0], [%1], 16;" :: "r"(d), "l"(s))
#define CP_COMMIT() asm volatile("cp.async.commit_group;" ::: "memory")
#define CP_WAIT2()  asm volatile("cp.async.wait_group 2;" ::: "memory")
// pair barrier: the 64 threads (2 warps) that both stage and read one B quarter
#define PAIR_BAR(id) asm volatile("bar.sync %0, 64;" :: "r"(id) : "memory")

__device__ __forceinline__ uint32_t smem_u32(const void* p) {
    uint32_t a;
    asm("{ .reg .u64 t; cvta.to.shared.u64 t, %1; cvt.u32.u64 %0, t; }" : "=r"(a) : "l"(p));
    return a;
}
// hardware tanh: 1 MUFU op
__device__ __forceinline__ float fast_tanh(float x) {
    float y;
    asm("tanh.approx.f32 %0, %1;" : "=f"(y) : "f"(x));
    return y;
}
__device__ __forceinline__ uint32_t h2u(float lo, float hi) {
    uint32_t r;
    asm("{ .reg .b16 l, h; cvt.rn.f16.f32 l, %1; cvt.rn.f16.f32 h, %2; mov.b32 %0, {l, h}; }"
        : "=r"(r) : "f"(lo), "f"(hi));
    return r;
}
__device__ __forceinline__ float2 uh2(uint32_t u) {
    __half2 h = *(__half2*)&u;
    return __half22float2(h);
}
__device__ __forceinline__ void mma16816(float d[4],
    uint32_t a0, uint32_t a1, uint32_t a2, uint32_t a3, uint32_t b0, uint32_t b1) {
    asm volatile("mma.sync.aligned.m16n8k16.row.col.f32.f16.f16.f32 "
                 "{%0,%1,%2,%3},{%4,%5,%6,%7},{%8,%9},{%0,%1,%2,%3};"
                 : "+f"(d[0]), "+f"(d[1]), "+f"(d[2]), "+f"(d[3])
                 : "r"(a0), "r"(a1), "r"(a2), "r"(a3), "r"(b0), "r"(b1));
}

// ---------- prepack ----------
__global__ void __launch_bounds__(512) prepack(const float* __restrict__ hW2,
                                               const float* __restrict__ fW2,
                                               const float* __restrict__ fW3,
                                               const float* __restrict__ hW1,
                                               const float* __restrict__ fW1) {
    int tid = blockIdx.x * 512 + threadIdx.x;
    if (tid < 65536) {
        int off = tid & 32767;
        const float* W = (tid >> 15) ? fW2 : hW2;
        // uint4-paired layout: wd selects (nt parity, br)
        int wd = off & 3, lane = (off >> 2) & 31, np = (off >> 7) & 15, kk = off >> 11;
        int nt = 2 * np + (wd >> 1), br = wd & 1;
        int n = nt * 8 + (lane >> 2), k = kk * 16 + 2 * (lane & 3) + br * 8;
        g_wpk[tid] = h2u(W[n * 256 + k], W[n * 256 + k + 1]);
    } else if (tid < 67584) {
        int off = tid - 65536;
        int br = off & 1, lane = (off >> 1) & 31, nf = (off >> 6) & 1, kk = off >> 7;
        int n = nf * 8 + (lane >> 2), k = kk * 16 + 2 * (lane & 3) + br * 8;
        g_wpk[tid] = h2u(fW3[n * 256 + k], fW3[n * 256 + k + 1]);
    } else if (tid < 71680) {
        int off = tid - 67584;
        const float* W = (off >= 2048) ? fW1 : hW1;
        off &= 2047;
        int br = off & 1, lane = (off >> 1) & 31, nf = off >> 6;
        int n = nf * 8 + (lane >> 2), k = 2 * (lane & 3) + br * 8;
        g_wpk[tid] = h2u(W[n * 16 + k], W[n * 16 + k + 1]);
    }
}

__device__ __forceinline__ void ring_issue(uint32_t ringb, const uint32_t* wsrc, int c, int t) {
    if (c < 16) {
        uint32_t dst = ringb + (uint32_t)(((c & 3) << 13) + (t << 5));
        const char* src = (const char*)(wsrc + (c << 11)) + (t << 5);
        CP_ASYNC16(dst, src);
        CP_ASYNC16(dst + 16, src + 16);
    }
    CP_COMMIT();
}

#define ZERO_ACC(acc) do { \
    _Pragma("unroll") for (int _m = 0; _m < 2; ++_m) \
    _Pragma("unroll") for (int _n = 0; _n < 8; ++_n) \
    _Pragma("unroll") for (int _i = 0; _i < 4; ++_i) (acc)[_m][_n][_i] = 0.0f; \
} while (0)

// Big GEMM: A frags from ab (smem), B streamed from wsrc via ring.
// Mainloop uses PAIR barriers only: the 64 staging threads of B-quarter wcol
// are exactly the two warps (wrow 0/1) that consume it.
// Prologue (chunks 0..2) must already be issued. Ends with a pair barrier.
__device__ __forceinline__ void gemm_ring(const uint4* __restrict__ ab, const char* smx,
                                          uint32_t ringb, const uint32_t* __restrict__ wsrc,
                                          int wrow, int wcol, int lane, int t,
                                          float acc[2][8][4]) {
    const int s0 = wrow * 2;
    const int bid = 1 + wcol;
#pragma unroll
    for (int kk = 0; kk < 16; ++kk) {
        CP_WAIT2();
        PAIR_BAR(bid);
        ring_issue(ringb, wsrc, kk + 3, t);
        const uint4* rb4 = (const uint4*)(smx + O_RING + ((kk & 3) << 13));
        uint4 A0 = ab[(s0 * 16 + kk) * 32 + lane];
        uint4 A1 = ab[((s0 + 1) * 16 + kk) * 32 + lane];
        uint4 B[4];
#pragma unroll
        for (int j = 0; j < 4; ++j)
            B[j] = rb4[((wcol << 2) + j) * 32 + lane];
#pragma unroll
        for (int j = 0; j < 4; ++j) {
            mma16816(acc[0][2*j],   A0.x, A0.y, A0.z, A0.w, B[j].x, B[j].y);
            mma16816(acc[1][2*j],   A1.x, A1.y, A1.z, A1.w, B[j].x, B[j].y);
            mma16816(acc[0][2*j+1], A0.x, A0.y, A0.z, A0.w, B[j].z, B[j].w);
            mma16816(acc[1][2*j+1], A1.x, A1.y, A1.z, A1.w, B[j].z, B[j].w);
        }
    }
    PAIR_BAR(bid);   // pair's ring reads done before slots reused by next prologue
}

__global__ void __launch_bounds__(NT, 2)
flexhnn_f16(const float* __restrict__ z,
            const float* __restrict__ hb1, const float* __restrict__ hb2,
            const float* __restrict__ fb1, const float* __restrict__ fb2,
            const float* __restrict__ fb3,
            float* __restrict__ out)
{
    extern __shared__ __align__(16) char smx[];
    float* smF = (float*)smx;
    uint4* sa4 = (uint4*)(smx + O_SA);
    uint4* sb4 = (uint4*)(smx + O_SB);
    const uint32_t ringb = smem_u32(smx) + O_RING;

    const int t = threadIdx.x, lane = t & 31, w = t >> 5;
    const int fr = lane >> 2, fc = lane & 3;
    const int wrow = w & 1, wcol = w >> 1;     // 8 warps: 2 row-halves x 4 col-quarters
    const long n0 = (long)blockIdx.x * BM;

    // ---- stage biases ----
    smF[O_HB1 / 4 + t] = hb1[t];
    smF[O_FB1 / 4 + t] = fb1[t];
    smF[O_HB2 / 4 + t] = hb2[t];
    smF[O_FB2 / 4 + t] = fb2[t];
    if (t < 16) smF[O_FB3 / 4 + t] = fb3[t];
    __syncthreads();

    // ---- GEMM1: z A-frags (fp16) ----
    uint4 Az[2];
#pragma unroll
    for (int mt = 0; mt < 2; ++mt) {
        const long rl = n0 + (wrow * 32 + mt * 16 + fr);
        float2 zl0 = *(const float2*)(z + rl * 16 + 2 * fc);
        float2 zl8 = *(const float2*)(z + rl * 16 + 2 * fc + 8);
        float2 zh0 = *(const float2*)(z + (rl + 8) * 16 + 2 * fc);
        float2 zh8 = *(const float2*)(z + (rl + 8) * 16 + 2 * fc + 8);
        Az[mt].x = h2u(zl0.x, zl0.y); Az[mt].y = h2u(zh0.x, zh0.y);
        Az[mt].z = h2u(zl8.x, zl8.y); Az[mt].w = h2u(zh8.x, zh8.y);
    }

    float acc[2][8][4];

    // ---- GEMM1a: a1 = z @ hW1^T ; epi1a: t1 -> SA frags ----
    ZERO_ACC(acc);
#pragma unroll
    for (int nt = 0; nt < 8; ++nt) {
        uint2 B = *(const uint2*)(g_wpk + 67584 + (((wcol << 3) + nt) * 32 + lane) * 2);
        mma16816(acc[0][nt], Az[0].x, Az[0].y, Az[0].z, Az[0].w, B.x, B.y);
        mma16816(acc[1][nt], Az[1].x, Az[1].y, Az[1].z, Az[1].w, B.x, B.y);
    }
#pragma unroll
    for (int mt = 0; mt < 2; ++mt) {
        const int strip = wrow * 2 + mt;
#pragma unroll
        for (int j = 0; j < 4; ++j) {
            const int kkc = wcol * 4 + j;
            const int c0 = (wcol << 6) + (j << 4) + 2 * fc;
            float2 bA = *(const float2*)(smF + O_HB1 / 4 + c0);
            float2 bB = *(const float2*)(smF + O_HB1 / 4 + c0 + 8);
            uint4 v;
            v.x = h2u(fast_tanh(acc[mt][2*j][0] + bA.x), fast_tanh(acc[mt][2*j][1] + bA.y));
            v.y = h2u(fast_tanh(acc[mt][2*j][2] + bA.x), fast_tanh(acc[mt][2*j][3] + bA.y));
            v.z = h2u(fast_tanh(acc[mt][2*j+1][0] + bB.x), fast_tanh(acc[mt][2*j+1][1] + bB.y));
            v.w = h2u(fast_tanh(acc[mt][2*j+1][2] + bB.x), fast_tanh(acc[mt][2*j+1][3] + bB.y));
            sa4[(strip * 16 + kkc) * 32 + lane] = v;
        }
    }

    // ---- GEMM1b: f = z @ fW1^T + fb1 ; epi1b: f -> SB frags ----
    ZERO_ACC(acc);
#pragma unroll
    for (int nt = 0; nt < 8; ++nt) {
        uint2 B = *(const uint2*)(g_wpk + 69632 + (((wcol << 3) + nt) * 32 + lane) * 2);
        mma16816(acc[0][nt], Az[0].x, Az[0].y, Az[0].z, Az[0].w, B.x, B.y);
        mma16816(acc[1][nt], Az[1].x, Az[1].y, Az[1].z, Az[1].w, B.x, B.y);
    }
#pragma unroll
    for (int mt = 0; mt < 2; ++mt) {
        const int strip = wrow * 2 + mt;
#pragma unroll
        for (int j = 0; j < 4; ++j) {
            const int kkc = wcol * 4 + j;
            const int c0 = (wcol << 6) + (j << 4) + 2 * fc;
            float2 bA = *(const float2*)(smF + O_FB1 / 4 + c0);
            float2 bB = *(const float2*)(smF + O_FB1 / 4 + c0 + 8);
            uint4 v;
            v.x = h2u(acc[mt][2*j][0] + bA.x, acc[mt][2*j][1] + bA.y);
            v.y = h2u(acc[mt][2*j][2] + bA.x, acc[mt][2*j][3] + bA.y);
            v.z = h2u(acc[mt][2*j+1][0] + bB.x, acc[mt][2*j+1][1] + bB.y);
            v.w = h2u(acc[mt][2*j+1][2] + bB.x, acc[mt][2*j+1][3] + bB.y);
            sb4[(strip * 16 + kkc) * 32 + lane] = v;
        }
    }

    // prologue for GEMM2 ring (hW2), then make SA/SB visible
    ring_issue(ringb, g_wpk, 0, t);
    ring_issue(ringb, g_wpk, 1, t);
    ring_issue(ringb, g_wpk, 2, t);
    __syncthreads();

    // ---- GEMM2: a2 = t1 @ hW2^T ----
    ZERO_ACC(acc);
    gemm_ring(sa4, smx, ringb, g_wpk, wrow, wcol, lane, t, acc);

    // prologue for GEMM3 ring (fW2) — overlaps epi2 (pair-local slot reuse is safe)
    ring_issue(ringb, g_wpk + 32768, 0, t);
    ring_issue(ringb, g_wpk + 32768, 1, t);
    ring_issue(ringb, g_wpk + 32768, 2, t);

    // ---- epi2: g = .5*f*s2 + .5*tanh(f)  (f from SB, overwrite with g) ----
#pragma unroll
    for (int mt = 0; mt < 2; ++mt) {
        const int strip = wrow * 2 + mt;
#pragma unroll
        for (int j = 0; j < 4; ++j) {
            const int kkc = wcol * 4 + j;
            const int c0 = (wcol << 6) + (j << 4) + 2 * fc;
            uint4* p = sb4 + (strip * 16 + kkc) * 32 + lane;
            uint4 fv = *p;
            float2 bA = *(const float2*)(smF + O_HB2 / 4 + c0);
            float2 bB = *(const float2*)(smF + O_HB2 / 4 + c0 + 8);
            float2 flo = uh2(fv.x), fhi = uh2(fv.y), glo = uh2(fv.z), ghi = uh2(fv.w);
            float t2, s2, fx;
            uint4 o;
            #define MIX(av, bb, ff) (t2 = fast_tanh((av) + (bb)), s2 = 1.0f - t2 * t2, \
                                     fx = (ff), 0.5f * (fx * s2) + 0.5f * fast_tanh(fx))
            o.x = h2u(MIX(acc[mt][2*j][0], bA.x, flo.x), MIX(acc[mt][2*j][1], bA.y, flo.y));
            o.y = h2u(MIX(acc[mt][2*j][2], bA.x, fhi.x), MIX(acc[mt][2*j][3], bA.y, fhi.y));
            o.z = h2u(MIX(acc[mt][2*j+1][0], bB.x, glo.x), MIX(acc[mt][2*j+1][1], bB.y, glo.y));
            o.w = h2u(MIX(acc[mt][2*j+1][2], bB.x, ghi.x), MIX(acc[mt][2*j+1][3], bB.y, ghi.y));
            #undef MIX
            *p = o;
        }
    }
    __syncthreads();

    // ---- GEMM3: f2 = g @ fW2^T ----
    ZERO_ACC(acc);
    gemm_ring(sb4, smx, ringb, g_wpk + 32768, wrow, wcol, lane, t, acc);

    // ---- epi3: h = .5*f2*s1 + .5*tanh(f2), s1 = 1 - t1^2 (t1 from SA, overwrite with h) ----
#pragma unroll
    for (int mt = 0; mt < 2; ++mt) {
        const int strip = wrow * 2 + mt;
#pragma unroll
        for (int j = 0; j < 4; ++j) {
            const int kkc = wcol * 4 + j;
            const int c0 = (wcol << 6) + (j << 4) + 2 * fc;
            uint4* p = sa4 + (strip * 16 + kkc) * 32 + lane;
            uint4 tv = *p;
            float2 bA = *(const float2*)(smF + O_FB2 / 4 + c0);
            float2 bB = *(const float2*)(smF + O_FB2 / 4 + c0 + 8);
            float2 tlo = uh2(tv.x), thi = uh2(tv.y), ulo = uh2(tv.z), uhi = uh2(tv.w);
            float f2, s1;
            uint4 o;
            #define HMX(av, bb, tt) (f2 = (av) + (bb), s1 = 1.0f - (tt) * (tt), \
                                     0.5f * (f2 * s1) + 0.5f * fast_tanh(f2))
            o.x = h2u(HMX(acc[mt][2*j][0], bA.x, tlo.x), HMX(acc[mt][2*j][1], bA.y, tlo.y));
            o.y = h2u(HMX(acc[mt][2*j][2], bA.x, thi.x), HMX(acc[mt][2*j][3], bA.y, thi.y));
            o.z = h2u(HMX(acc[mt][2*j+1][0], bB.x, ulo.x), HMX(acc[mt][2*j+1][1], bB.y, ulo.y));
            o.w = h2u(HMX(acc[mt][2*j+1][2], bB.x, uhi.x), HMX(acc[mt][2*j+1][3], bB.y, uhi.y));
            #undef HMX
            *p = o;
        }
    }
    __syncthreads();

    // ---- GEMM4: o = h @ fW3^T ; symplectic swap -> out ----
    {
        const int strip = w >> 1, nf4 = w & 1;
        uint2 B[16];
#pragma unroll
        for (int kk = 0; kk < 16; ++kk)
            B[kk] = *(const uint2*)(g_wpk + 65536 + (((kk * 2 + nf4) * 32 + lane) * 2));
        float o[4] = {0.0f, 0.0f, 0.0f, 0.0f};
#pragma unroll
        for (int kk = 0; kk < 16; ++kk) {
            uint4 A = sa4[(strip * 16 + kk) * 32 + lane];
            mma16816(o, A.x, A.y, A.z, A.w, B[kk].x, B[kk].y);
        }
        const int j0 = nf4 * 8 + 2 * fc;
        const int dst = (j0 + 8) & 15;
        const float sgn = (j0 < 8) ? -1.0f : 1.0f;
        const float b0 = smF[O_FB3 / 4 + j0], b1 = smF[O_FB3 / 4 + j0 + 1];
        const long rlo = n0 + strip * 16 + fr;
        *(float2*)(out + rlo * 16 + dst)       = make_float2(sgn * (o[0] + b0), sgn * (o[1] + b1));
        *(float2*)(out + (rlo + 8) * 16 + dst) = make_float2(sgn * (o[2] + b0), sgn * (o[3] + b1));
    }
}

extern "C" void kernel_launch(void* const* d_in, const int* in_sizes, int n_in,
                              void* d_out, int out_size)
{
    // metadata order: t, z, hW1, hb1, hW2, hb2, fW1, fb1, fW2, fb2, fW3, fb3
    const float* z   = (const float*)d_in[1];
    const float* hW1 = (const float*)d_in[2];
    const float* hb1 = (const float*)d_in[3];
    const float* hW2 = (const float*)d_in[4];
    const float* hb2 = (const float*)d_in[5];
    const float* fW1 = (const float*)d_in[6];
    const float* fb1 = (const float*)d_in[7];
    const float* fW2 = (const float*)d_in[8];
    const float* fb2 = (const float*)d_in[9];
    const float* fW3 = (const float*)d_in[10];
    const float* fb3 = (const float*)d_in[11];
    float* out = (float*)d_out;

    const int n = in_sizes[1] / 16;          // 131072 rows
    const int grid = n / BM;                 // 2048 CTAs

    prepack<<<140, 512>>>(hW2, fW2, fW3, hW1, fW1);

    cudaFuncSetAttribute(flexhnn_f16,
                         cudaFuncAttributeMaxDynamicSharedMemorySize, SMEMB);
    flexhnn_f16<<<grid, NT, SMEMB>>>(z, hb1, hb2, fb1, fb2, fb3, out);
}